// round 1
// baseline (speedup 1.0000x reference)
#include <cuda_runtime.h>
#include <cuda_fp16.h>
#include <cstdint>

// Problem constants
constexpr int Bc = 8, Sc = 2048, Dc = 2048, Rc = 256;
constexpr int NTOK = Bc * Sc;            // 16384

// Scratch (no cudaMalloc allowed)
__device__ __half g_h[NTOK * Rc];        // intermediate h, fp16  (8 MB)
__device__ __half g_wi[Dc * Rc];         // prepped weight_in fp16
__device__ __half g_wo[Rc * Dc];         // prepped weight_out fp16

// ---------------------------------------------------------------------------
// 2:4 soft-threshold weight prep: groups of 4 along last (contiguous) dim.
// t = 2nd smallest |w| of group; out = sign(w)*max(|w|-t,0)*scale -> fp16
// ---------------------------------------------------------------------------
__global__ void prep_weights_kernel(const float* __restrict__ W,
                                    const float* __restrict__ scale,
                                    __half* __restrict__ out, int ngroups)
{
    int g = blockIdx.x * blockDim.x + threadIdx.x;
    if (g >= ngroups) return;
    float s = scale[0];
    float4 w = reinterpret_cast<const float4*>(W)[g];
    float a0 = fabsf(w.x), a1 = fabsf(w.y), a2 = fabsf(w.z), a3 = fabsf(w.w);
    float lo01 = fminf(a0, a1), hi01 = fmaxf(a0, a1);
    float lo23 = fminf(a2, a3), hi23 = fmaxf(a2, a3);
    float t = fminf(fmaxf(lo01, lo23), fminf(hi01, hi23)); // 2nd smallest of 4
    float r0 = copysignf(fmaxf(a0 - t, 0.f), w.x) * s;
    float r1 = copysignf(fmaxf(a1 - t, 0.f), w.y) * s;
    float r2 = copysignf(fmaxf(a2 - t, 0.f), w.z) * s;
    float r3 = copysignf(fmaxf(a3 - t, 0.f), w.w) * s;
    __half2* o = reinterpret_cast<__half2*>(out + (size_t)g * 4);
    o[0] = __floats2half2_rn(r0, r1);
    o[1] = __floats2half2_rn(r2, r3);
}

// ---------------------------------------------------------------------------
// Tensor-core GEMM: C[M,N] = A[M,K] * B[K,N] + bias[N]
// A: fp32 (converted to fp16 on smem store) or fp16. C: fp16 or fp32.
// mma.sync.m16n8k16 + ldmatrix; warp tile 32x64; reg-staged double buffer.
// Requires M%BM==0, N%BN==0, K%BK==0 (true for all shapes here).
// ---------------------------------------------------------------------------
__device__ __forceinline__ uint32_t smem_u32(const void* p) {
    return (uint32_t)__cvta_generic_to_shared(p);
}

__device__ __forceinline__ void mma16816(float* d, const uint32_t* a,
                                         uint32_t b0, uint32_t b1) {
    asm volatile(
        "mma.sync.aligned.m16n8k16.row.col.f32.f16.f16.f32 "
        "{%0,%1,%2,%3}, {%4,%5,%6,%7}, {%8,%9}, {%0,%1,%2,%3};\n"
        : "+f"(d[0]), "+f"(d[1]), "+f"(d[2]), "+f"(d[3])
        : "r"(a[0]), "r"(a[1]), "r"(a[2]), "r"(a[3]), "r"(b0), "r"(b1));
}

template <typename AT, typename CT, int BM, int BN, int BK, int WARPS_M, int WARPS_N>
__global__ __launch_bounds__(256) void gemm_tc(
    const AT* __restrict__ A, const __half* __restrict__ Bw,
    const float* __restrict__ bias, CT* __restrict__ C,
    int M, int N, int K)
{
    constexpr int WM = BM / WARPS_M;   // 32
    constexpr int WN = BN / WARPS_N;   // 64
    constexpr int MI = WM / 16;        // 2
    constexpr int NI = WN / 16;        // 4
    constexpr int APAD = 8, BPAD = 8;
    constexpr int ASTR = BK + APAD;
    constexpr int BSTR = BN + BPAD;

    __shared__ __half As[2][BM][ASTR];
    __shared__ __half Bs[2][BK][BSTR];

    const int tid  = threadIdx.x;
    const int warp = tid >> 5, lane = tid & 31;
    const int wm = warp % WARPS_M;
    const int wn = warp / WARPS_M;
    const int m0 = blockIdx.y * BM;
    const int n0 = blockIdx.x * BN;

    constexpr int A_F4 = (BM * BK) / (256 * 4);  // float4 per thread (fp32 A)
    constexpr int A_C8 = (BM * BK) / (256 * 8);  // 8-half chunks per thread (fp16 A)
    constexpr int B_C8 = (BK * BN) / (256 * 8);
    constexpr int BCH  = BN / 8;                 // 8-half chunks per B row

    float4 aF[(A_F4 > 0) ? A_F4 : 1];
    uint4  aH[(A_C8 > 0) ? A_C8 : 1];
    uint4  bR[B_C8];

    auto ldg_tile = [&](int kt) {
        const int k0 = kt * BK;
        if constexpr (sizeof(AT) == 4) {
            #pragma unroll
            for (int i = 0; i < A_F4; i++) {
                int f = tid + i * 256;
                int row = f >> 3, c4 = f & 7;              // 8 float4 per row (BK=32)
                aF[i] = *reinterpret_cast<const float4*>(
                    (const float*)A + (size_t)(m0 + row) * K + k0 + c4 * 4);
            }
        } else {
            #pragma unroll
            for (int i = 0; i < A_C8; i++) {
                int c = tid + i * 256;
                int row = c >> 2, cc = c & 3;              // 4 chunks per row (BK=32)
                aH[i] = *reinterpret_cast<const uint4*>(
                    (const __half*)A + (size_t)(m0 + row) * K + k0 + cc * 8);
            }
        }
        #pragma unroll
        for (int i = 0; i < B_C8; i++) {
            int c = tid + i * 256;
            int row = c / BCH, cc = c % BCH;
            bR[i] = *reinterpret_cast<const uint4*>(
                Bw + (size_t)(k0 + row) * N + n0 + cc * 8);
        }
    };

    auto sts_tile = [&](int buf) {
        if constexpr (sizeof(AT) == 4) {
            #pragma unroll
            for (int i = 0; i < A_F4; i++) {
                int f = tid + i * 256;
                int row = f >> 3, c4 = f & 7;
                __half2 h01 = __floats2half2_rn(aF[i].x, aF[i].y);
                __half2 h23 = __floats2half2_rn(aF[i].z, aF[i].w);
                uint2 u;
                u.x = *reinterpret_cast<uint32_t*>(&h01);
                u.y = *reinterpret_cast<uint32_t*>(&h23);
                *reinterpret_cast<uint2*>(&As[buf][row][c4 * 4]) = u;
            }
        } else {
            #pragma unroll
            for (int i = 0; i < A_C8; i++) {
                int c = tid + i * 256;
                int row = c >> 2, cc = c & 3;
                *reinterpret_cast<uint4*>(&As[buf][row][cc * 8]) = aH[i];
            }
        }
        #pragma unroll
        for (int i = 0; i < B_C8; i++) {
            int c = tid + i * 256;
            int row = c / BCH, cc = c % BCH;
            *reinterpret_cast<uint4*>(&Bs[buf][row][cc * 8]) = bR[i];
        }
    };

    float acc[MI][2 * NI][4];
    #pragma unroll
    for (int mi = 0; mi < MI; mi++)
        #pragma unroll
        for (int nn = 0; nn < 2 * NI; nn++)
            #pragma unroll
            for (int j = 0; j < 4; j++) acc[mi][nn][j] = 0.f;

    const int KT = K / BK;
    ldg_tile(0);
    sts_tile(0);
    __syncthreads();

    for (int kt = 0; kt < KT; kt++) {
        const int cur = kt & 1;
        if (kt + 1 < KT) ldg_tile(kt + 1);

        #pragma unroll
        for (int ks = 0; ks < BK / 16; ks++) {
            uint32_t af[MI][4], bf[NI][4];
            #pragma unroll
            for (int mi = 0; mi < MI; mi++) {
                uint32_t addr = smem_u32(
                    &As[cur][wm * WM + mi * 16 + (lane & 15)][ks * 16 + ((lane >> 4) << 3)]);
                asm volatile("ldmatrix.sync.aligned.m8n8.x4.shared.b16 {%0,%1,%2,%3}, [%4];\n"
                             : "=r"(af[mi][0]), "=r"(af[mi][1]), "=r"(af[mi][2]), "=r"(af[mi][3])
                             : "r"(addr));
            }
            #pragma unroll
            for (int ni = 0; ni < NI; ni++) {
                uint32_t addr = smem_u32(
                    &Bs[cur][ks * 16 + (lane & 15)][wn * WN + ni * 16 + ((lane >> 4) << 3)]);
                asm volatile("ldmatrix.sync.aligned.m8n8.x4.trans.shared.b16 {%0,%1,%2,%3}, [%4];\n"
                             : "=r"(bf[ni][0]), "=r"(bf[ni][1]), "=r"(bf[ni][2]), "=r"(bf[ni][3])
                             : "r"(addr));
            }
            #pragma unroll
            for (int mi = 0; mi < MI; mi++)
                #pragma unroll
                for (int ni = 0; ni < NI; ni++) {
                    mma16816(acc[mi][2 * ni],     af[mi], bf[ni][0], bf[ni][1]);
                    mma16816(acc[mi][2 * ni + 1], af[mi], bf[ni][2], bf[ni][3]);
                }
        }

        if (kt + 1 < KT) {
            sts_tile((kt + 1) & 1);   // writes the buffer everyone finished reading last iter
            __syncthreads();
        }
    }

    // Epilogue: add bias, write C
    const int gID = lane >> 2;
    const int tc  = (lane & 3) * 2;
    #pragma unroll
    for (int mi = 0; mi < MI; mi++) {
        #pragma unroll
        for (int nn = 0; nn < 2 * NI; nn++) {
            int col = n0 + wn * WN + nn * 8 + tc;
            float b0 = bias[col], b1 = bias[col + 1];
            int row = m0 + wm * WM + mi * 16 + gID;
            float v0 = acc[mi][nn][0] + b0;
            float v1 = acc[mi][nn][1] + b1;
            float v2 = acc[mi][nn][2] + b0;
            float v3 = acc[mi][nn][3] + b1;
            if constexpr (sizeof(CT) == 2) {
                *reinterpret_cast<__half2*>(&((__half*)C)[(size_t)row * N + col])       = __floats2half2_rn(v0, v1);
                *reinterpret_cast<__half2*>(&((__half*)C)[(size_t)(row + 8) * N + col]) = __floats2half2_rn(v2, v3);
            } else {
                *reinterpret_cast<float2*>(&((float*)C)[(size_t)row * N + col])       = make_float2(v0, v1);
                *reinterpret_cast<float2*>(&((float*)C)[(size_t)(row + 8) * N + col]) = make_float2(v2, v3);
            }
        }
    }
}

// ---------------------------------------------------------------------------
extern "C" void kernel_launch(void* const* d_in, const int* in_sizes, int n_in,
                              void* d_out, int out_size)
{
    const float* x     = (const float*)d_in[0];
    const float* w_in  = (const float*)d_in[1];
    const float* w_out = (const float*)d_in[2];
    const float* b_in  = (const float*)d_in[3];
    const float* b_out = (const float*)d_in[4];
    const float* s_in  = (const float*)d_in[5];
    const float* s_out = (const float*)d_in[6];

    __half *wi, *wo, *h;
    cudaGetSymbolAddress((void**)&wi, g_wi);
    cudaGetSymbolAddress((void**)&wo, g_wo);
    cudaGetSymbolAddress((void**)&h,  g_h);

    const int ng = Dc * Rc / 4;  // 131072 groups, same count both layers
    prep_weights_kernel<<<(ng + 255) / 256, 256>>>(w_in,  s_in,  wi, ng);
    prep_weights_kernel<<<(ng + 255) / 256, 256>>>(w_out, s_out, wo, ng);

    // GEMM1: h = fp16( x @ w_in_sparse + bias_in )   [16384,256], full-N CTA => x read once
    gemm_tc<float, __half, 64, 256, 32, 2, 4>
        <<<dim3(Rc / 256, NTOK / 64), 256>>>(x, wi, b_in, h, NTOK, Rc, Dc);

    // GEMM2: y = fp32( h @ w_out_sparse + bias_out ) [16384,2048]
    gemm_tc<__half, float, 128, 128, 32, 4, 2>
        <<<dim3(Dc / 128, NTOK / 128), 256>>>(h, wo, b_out, (float*)d_out, NTOK, Dc, Rc);
}

// round 3
// speedup vs baseline: 1.0210x; 1.0210x over previous
#include <cuda_runtime.h>
#include <cuda_fp16.h>
#include <cstdint>

// Problem constants
constexpr int Dc = 2048, Rc = 256, NTOK = 16384;

// Scratch (no cudaMalloc allowed)
__device__ __half g_h[NTOK * Rc];       // intermediate h, fp16 (8 MB)
__device__ __half g_wiT[Rc * Dc];       // prepped weight_in,  transposed [N=R, K=D]
__device__ __half g_woT[Dc * Rc];       // prepped weight_out, transposed [N=D, K=R]

// ---------------------------------------------------------------------------
// Helpers
// ---------------------------------------------------------------------------
__device__ __forceinline__ uint32_t smem_u32(const void* p) {
    uint32_t a;
    asm("{ .reg .u64 t; cvta.to.shared.u64 t, %1; cvt.u32.u64 %0, t; }" : "=r"(a) : "l"(p));
    return a;
}
__device__ __forceinline__ uint32_t swz128(uint32_t off) { return off ^ ((off >> 3) & 0x70); }

#define CP_ASYNC16(dst, src) asm volatile("cp.async.cg.shared.global [%0], [%1], 16;" :: "r"(dst), "l"(src))
#define CP_COMMIT()          asm volatile("cp.async.commit_group;" ::: "memory")
template <int N> __device__ __forceinline__ void cp_wait() {
    asm volatile("cp.async.wait_group %0;" :: "n"(N) : "memory");
}

__device__ __forceinline__ void ldsm4(uint32_t* r, uint32_t addr) {
    asm volatile("ldmatrix.sync.aligned.m8n8.x4.shared.b16 {%0,%1,%2,%3}, [%4];"
                 : "=r"(r[0]), "=r"(r[1]), "=r"(r[2]), "=r"(r[3]) : "r"(addr));
}
__device__ __forceinline__ void mma16816(float* d, const uint32_t* a,
                                         uint32_t b0, uint32_t b1) {
    asm volatile(
        "mma.sync.aligned.m16n8k16.row.col.f32.f16.f16.f32 "
        "{%0,%1,%2,%3}, {%4,%5,%6,%7}, {%8,%9}, {%0,%1,%2,%3};\n"
        : "+f"(d[0]), "+f"(d[1]), "+f"(d[2]), "+f"(d[3])
        : "r"(a[0]), "r"(a[1]), "r"(a[2]), "r"(a[3]), "r"(b0), "r"(b1));
}

// ---------------------------------------------------------------------------
// 2:4 soft-threshold prep, output TRANSPOSED to [N, K] fp16 (K-major).
// W: [Kd, Nd] row-major, groups of 4 along Nd (last dim).
// ---------------------------------------------------------------------------
__global__ void prep_weights_T(const float* __restrict__ W, const float* __restrict__ scale,
                               __half* __restrict__ Wt, int Kd, int Nd)
{
    int t = blockIdx.x * blockDim.x + threadIdx.x;
    int nk = Kd >> 2;
    if (t >= nk * (Nd >> 2)) return;
    int k0 = (t % nk) << 2;
    int n0 = (t / nk) << 2;
    float s = scale[0];
    __half o[4][4];
    #pragma unroll
    for (int i = 0; i < 4; i++) {
        float4 w = *reinterpret_cast<const float4*>(W + (size_t)(k0 + i) * Nd + n0);
        float a0 = fabsf(w.x), a1 = fabsf(w.y), a2 = fabsf(w.z), a3 = fabsf(w.w);
        float lo01 = fminf(a0, a1), hi01 = fmaxf(a0, a1);
        float lo23 = fminf(a2, a3), hi23 = fmaxf(a2, a3);
        float th = fminf(fmaxf(lo01, lo23), fminf(hi01, hi23));
        o[i][0] = __float2half(copysignf(fmaxf(a0 - th, 0.f), w.x) * s);
        o[i][1] = __float2half(copysignf(fmaxf(a1 - th, 0.f), w.y) * s);
        o[i][2] = __float2half(copysignf(fmaxf(a2 - th, 0.f), w.z) * s);
        o[i][3] = __float2half(copysignf(fmaxf(a3 - th, 0.f), w.w) * s);
    }
    #pragma unroll
    for (int j = 0; j < 4; j++) {
        __half2 p0 = __halves2half2(o[0][j], o[1][j]);
        __half2 p1 = __halves2half2(o[2][j], o[3][j]);
        uint2 u;
        u.x = *reinterpret_cast<uint32_t*>(&p0);
        u.y = *reinterpret_cast<uint32_t*>(&p1);
        *reinterpret_cast<uint2*>(Wt + (size_t)(n0 + j) * Kd + k0) = u;
    }
}

// ---------------------------------------------------------------------------
// GEMM1: h[16384,256] = fp16( x[16384,2048] @ wiT[256,2048]^T + bias )
// CTA 128x256 (full N -> x read once), BK=64, 8 warps (warp tile 64x64).
// A fp32: LDG->regs->cvt->STS (2 buffers). B fp16: cp.async 3-stage.
// ---------------------------------------------------------------------------
__global__ __launch_bounds__(256) void gemm1_kernel(
    const float* __restrict__ A, const __half* __restrict__ Bt,
    const float* __restrict__ bias, __half* __restrict__ C)
{
    constexpr int KT = 2048 / 64;  // 32
    extern __shared__ char smem[];
    const uint32_t sb = smem_u32(smem);
    const int tid = threadIdx.x, wid = tid >> 5, lane = tid & 31;
    const int wm = wid >> 2, wn = wid & 3;   // 2 x 4 warps, warp tile 64x64
    const int m0 = blockIdx.x * 128;

    auto Aoff = [&](int b) { return sb + b * 16384u; };           // 2 x 16KB
    auto Boff = [&](int s) { return sb + 32768u + s * 32768u; };  // 3 x 32KB

    // --- A: fp32 reg staging (thread -> half a row: 32 floats) ---
    float4 aR[8];
    const int arow = tid >> 1, ahalf = tid & 1;
    auto ldgA = [&](int kt) {
        const float* p = A + (size_t)(m0 + arow) * 2048 + kt * 64 + ahalf * 32;
        #pragma unroll
        for (int j = 0; j < 8; j++) aR[j] = *reinterpret_cast<const float4*>(p + j * 4);
    };
    auto stsA = [&](int b) {
        #pragma unroll
        for (int jj = 0; jj < 4; jj++) {
            __half2 h0 = __floats2half2_rn(aR[2*jj].x,   aR[2*jj].y);
            __half2 h1 = __floats2half2_rn(aR[2*jj].z,   aR[2*jj].w);
            __half2 h2 = __floats2half2_rn(aR[2*jj+1].x, aR[2*jj+1].y);
            __half2 h3 = __floats2half2_rn(aR[2*jj+1].z, aR[2*jj+1].w);
            uint32_t u0 = *reinterpret_cast<uint32_t*>(&h0);
            uint32_t u1 = *reinterpret_cast<uint32_t*>(&h1);
            uint32_t u2 = *reinterpret_cast<uint32_t*>(&h2);
            uint32_t u3 = *reinterpret_cast<uint32_t*>(&h3);
            uint32_t dst = Aoff(b) + swz128((uint32_t)(arow * 128 + (ahalf * 4 + jj) * 16));
            asm volatile("st.shared.v4.b32 [%0], {%1,%2,%3,%4};"
                         :: "r"(dst), "r"(u0), "r"(u1), "r"(u2), "r"(u3) : "memory");
        }
    };
    // --- B: cp.async, tile 256 rows x 128B ---
    auto ldB = [&](int kt, int s) {
        #pragma unroll
        for (int i = 0; i < 8; i++) {
            int c = tid + i * 256, row = c >> 3, cc = c & 7;
            uint32_t dst = Boff(s) + swz128((uint32_t)(row * 128 + cc * 16));
            const __half* src = Bt + (size_t)row * 2048 + kt * 64 + cc * 8;
            CP_ASYNC16(dst, src);
        }
    };

    float acc[4][8][4];
    #pragma unroll
    for (int mi = 0; mi < 4; mi++)
        #pragma unroll
        for (int nn = 0; nn < 8; nn++)
            #pragma unroll
            for (int j = 0; j < 4; j++) acc[mi][nn][j] = 0.f;

    auto compute = [&](int ab, int bs) {
        const uint32_t Ab = Aoff(ab), Bb = Boff(bs);
        #pragma unroll
        for (int ks = 0; ks < 4; ks++) {
            const uint32_t chunk = (uint32_t)((ks * 2 + (lane >> 4)) * 16);
            uint32_t af[4][4], bf[4][4];
            #pragma unroll
            for (int mi = 0; mi < 4; mi++)
                ldsm4(af[mi], Ab + swz128((uint32_t)((wm*64 + mi*16 + (lane&15)) * 128) + chunk));
            #pragma unroll
            for (int ni = 0; ni < 4; ni++)
                ldsm4(bf[ni], Bb + swz128((uint32_t)((wn*64 + ni*16 + (lane&15)) * 128) + chunk));
            #pragma unroll
            for (int mi = 0; mi < 4; mi++)
                #pragma unroll
                for (int ni = 0; ni < 4; ni++) {
                    mma16816(acc[mi][2*ni],   af[mi], bf[ni][0], bf[ni][2]);
                    mma16816(acc[mi][2*ni+1], af[mi], bf[ni][1], bf[ni][3]);
                }
        }
    };

    // Prologue
    ldgA(0); stsA(0);
    ldB(0, 0); CP_COMMIT();
    ldB(1, 1); CP_COMMIT();
    ldgA(1);

    for (int kt = 0; kt < KT; kt++) {
        if (kt < KT - 1) cp_wait<1>(); else cp_wait<0>();
        __syncthreads();
        if (kt + 2 < KT) { ldB(kt + 2, (kt + 2) % 3); CP_COMMIT(); }
        compute(kt & 1, kt % 3);
        if (kt + 1 < KT) {
            stsA((kt + 1) & 1);
            if (kt + 2 < KT) ldgA(kt + 2);
        }
    }
    __syncthreads();

    // Epilogue: stage 128 x 264 halfs -> coalesced 16B stores
    __half* stg = reinterpret_cast<__half*>(smem);
    const int g = lane >> 2, tc = (lane & 3) * 2;
    #pragma unroll
    for (int mi = 0; mi < 4; mi++)
        #pragma unroll
        for (int nn = 0; nn < 8; nn++) {
            int row = wm * 64 + mi * 16 + g;
            int col = wn * 64 + (nn >> 1) * 16 + (nn & 1) * 8 + tc;
            float b0 = bias[col], b1 = bias[col + 1];
            *reinterpret_cast<__half2*>(stg + row * 264 + col) =
                __floats2half2_rn(acc[mi][nn][0] + b0, acc[mi][nn][1] + b1);
            *reinterpret_cast<__half2*>(stg + (row + 8) * 264 + col) =
                __floats2half2_rn(acc[mi][nn][2] + b0, acc[mi][nn][3] + b1);
        }
    __syncthreads();
    #pragma unroll
    for (int i = 0; i < 16; i++) {
        int chunk = tid + i * 256;
        int row = chunk >> 5, c = chunk & 31;
        uint4 v = *reinterpret_cast<uint4*>(stg + row * 264 + c * 8);
        *reinterpret_cast<uint4*>(C + (size_t)(m0 + row) * 256 + c * 8) = v;
    }
}

// ---------------------------------------------------------------------------
// GEMM2: y[16384,2048] = fp32( h[16384,256] @ woT[2048,256]^T + bias )
// CTA 128x128, BK=64, 4 warps (warp tile 64x64), cp.async 3-stage both ops.
// ---------------------------------------------------------------------------
__global__ __launch_bounds__(128, 2) void gemm2_kernel(
    const __half* __restrict__ A, const __half* __restrict__ Bt,
    const float* __restrict__ bias, float* __restrict__ C)
{
    constexpr int KT = 256 / 64;  // 4
    extern __shared__ char smem[];
    const uint32_t sb = smem_u32(smem);
    const int tid = threadIdx.x, wid = tid >> 5, lane = tid & 31;
    const int wm = wid >> 1, wn = wid & 1;   // 2 x 2 warps, warp tile 64x64
    const int m0 = blockIdx.y * 128;
    const int n0 = blockIdx.x * 128;

    auto Aoff = [&](int s) { return sb + s * 16384u; };
    auto Boff = [&](int s) { return sb + 49152u + s * 16384u; };

    auto ldTile = [&](int kt, int s) {
        #pragma unroll
        for (int i = 0; i < 8; i++) {
            int c = tid + i * 128, row = c >> 3, cc = c & 7;
            uint32_t sw = swz128((uint32_t)(row * 128 + cc * 16));
            CP_ASYNC16(Aoff(s) + sw, A  + (size_t)(m0 + row) * 256 + kt * 64 + cc * 8);
            CP_ASYNC16(Boff(s) + sw, Bt + (size_t)(n0 + row) * 256 + kt * 64 + cc * 8);
        }
    };

    float acc[4][8][4];
    #pragma unroll
    for (int mi = 0; mi < 4; mi++)
        #pragma unroll
        for (int nn = 0; nn < 8; nn++)
            #pragma unroll
            for (int j = 0; j < 4; j++) acc[mi][nn][j] = 0.f;

    auto compute = [&](int s) {
        const uint32_t Ab = Aoff(s), Bb = Boff(s);
        #pragma unroll
        for (int ks = 0; ks < 4; ks++) {
            const uint32_t chunk = (uint32_t)((ks * 2 + (lane >> 4)) * 16);
            uint32_t af[4][4], bf[4][4];
            #pragma unroll
            for (int mi = 0; mi < 4; mi++)
                ldsm4(af[mi], Ab + swz128((uint32_t)((wm*64 + mi*16 + (lane&15)) * 128) + chunk));
            #pragma unroll
            for (int ni = 0; ni < 4; ni++)
                ldsm4(bf[ni], Bb + swz128((uint32_t)((wn*64 + ni*16 + (lane&15)) * 128) + chunk));
            #pragma unroll
            for (int mi = 0; mi < 4; mi++)
                #pragma unroll
                for (int ni = 0; ni < 4; ni++) {
                    mma16816(acc[mi][2*ni],   af[mi], bf[ni][0], bf[ni][2]);
                    mma16816(acc[mi][2*ni+1], af[mi], bf[ni][1], bf[ni][3]);
                }
        }
    };

    ldTile(0, 0); CP_COMMIT();
    ldTile(1, 1); CP_COMMIT();

    for (int kt = 0; kt < KT; kt++) {
        if (kt < KT - 1) cp_wait<1>(); else cp_wait<0>();
        __syncthreads();
        if (kt + 2 < KT) { ldTile(kt + 2, (kt + 2) % 3); CP_COMMIT(); }
        compute(kt % 3);
    }
    __syncthreads();

    // Epilogue: 2 rounds (64 rows each), stage fp32 (stride 132) -> 16B stores
    float* stg = reinterpret_cast<float*>(smem);
    const int g = lane >> 2, tc = (lane & 3) * 2;
    #pragma unroll
    for (int r = 0; r < 2; r++) {
        if (wm == r) {
            #pragma unroll
            for (int mi = 0; mi < 4; mi++)
                #pragma unroll
                for (int nn = 0; nn < 8; nn++) {
                    int row = mi * 16 + g;
                    int col = wn * 64 + (nn >> 1) * 16 + (nn & 1) * 8 + tc;
                    float b0 = bias[n0 + col], b1 = bias[n0 + col + 1];
                    *reinterpret_cast<float2*>(stg + row * 132 + col) =
                        make_float2(acc[mi][nn][0] + b0, acc[mi][nn][1] + b1);
                    *reinterpret_cast<float2*>(stg + (row + 8) * 132 + col) =
                        make_float2(acc[mi][nn][2] + b0, acc[mi][nn][3] + b1);
                }
        }
        __syncthreads();
        #pragma unroll
        for (int i = 0; i < 16; i++) {
            int chunk = tid + i * 128;
            int row = chunk >> 5, c = chunk & 31;
            uint4 v = *reinterpret_cast<uint4*>(stg + row * 132 + c * 4);
            *reinterpret_cast<uint4*>(C + (size_t)(m0 + r * 64 + row) * 2048 + n0 + c * 4) = v;
        }
        __syncthreads();
    }
}

// ---------------------------------------------------------------------------
extern "C" void kernel_launch(void* const* d_in, const int* in_sizes, int n_in,
                              void* d_out, int out_size)
{
    const float* x     = (const float*)d_in[0];
    const float* w_in  = (const float*)d_in[1];
    const float* w_out = (const float*)d_in[2];
    const float* b_in  = (const float*)d_in[3];
    const float* b_out = (const float*)d_in[4];
    const float* s_in  = (const float*)d_in[5];
    const float* s_out = (const float*)d_in[6];

    __half *wiT, *woT, *h;
    cudaGetSymbolAddress((void**)&wiT, g_wiT);
    cudaGetSymbolAddress((void**)&woT, g_woT);
    cudaGetSymbolAddress((void**)&h,   g_h);

    constexpr int SMEM1 = 131072;  // A 2x16KB + B 3x32KB  (epilogue reuses)
    constexpr int SMEM2 = 98304;   // A 3x16KB + B 3x16KB
    cudaFuncSetAttribute(gemm1_kernel, cudaFuncAttributeMaxDynamicSharedMemorySize, SMEM1);
    cudaFuncSetAttribute(gemm2_kernel, cudaFuncAttributeMaxDynamicSharedMemorySize, SMEM2);

    // Prep: 2:4 soft-threshold + scale + transpose to [N,K] fp16
    prep_weights_T<<<128, 256>>>(w_in,  s_in,  wiT, Dc, Rc);   // -> [256, 2048]
    prep_weights_T<<<128, 256>>>(w_out, s_out, woT, Rc, Dc);   // -> [2048, 256]

    // GEMM1: h = fp16(x @ wi + b_in); grid 128 CTAs (one per 128 rows)
    gemm1_kernel<<<dim3(128), 256, SMEM1>>>(x, wiT, b_in, h);

    // GEMM2: y = fp32(h @ wo + b_out); grid 16 x 128
    gemm2_kernel<<<dim3(16, 128), 128, SMEM2>>>(h, woT, b_out, (float*)d_out);
}

// round 5
// speedup vs baseline: 1.0327x; 1.0114x over previous
#include <cuda_runtime.h>
#include <cuda_fp16.h>
#include <cstdint>

// Problem constants
constexpr int Dc = 2048, Rc = 256, NTOK = 16384;

// Scratch (no cudaMalloc allowed)
__device__ __half g_h[NTOK * Rc];       // intermediate h, fp16 (8 MB)
__device__ __half g_wiT[Rc * Dc];       // prepped weight_in,  transposed [N=R, K=D]
__device__ __half g_woT[Dc * Rc];       // prepped weight_out, transposed [N=D, K=R]

// ---------------------------------------------------------------------------
// Helpers
// ---------------------------------------------------------------------------
__device__ __forceinline__ uint32_t smem_u32(const void* p) {
    uint32_t a;
    asm("{ .reg .u64 t; cvta.to.shared.u64 t, %1; cvt.u32.u64 %0, t; }" : "=r"(a) : "l"(p));
    return a;
}

#define CP_ASYNC16(dst, src) asm volatile("cp.async.cg.shared.global [%0], [%1], 16;" :: "r"(dst), "l"(src))
#define CP_COMMIT()          asm volatile("cp.async.commit_group;" ::: "memory")
template <int N> __device__ __forceinline__ void cp_wait() {
    asm volatile("cp.async.wait_group %0;" :: "n"(N) : "memory");
}

__device__ __forceinline__ void ldsm4(uint32_t* r, uint32_t addr) {
    asm volatile("ldmatrix.sync.aligned.m8n8.x4.shared.b16 {%0,%1,%2,%3}, [%4];"
                 : "=r"(r[0]), "=r"(r[1]), "=r"(r[2]), "=r"(r[3]) : "r"(addr));
}
__device__ __forceinline__ void mma16816(float* d, const uint32_t* a,
                                         uint32_t b0, uint32_t b1) {
    asm volatile(
        "mma.sync.aligned.m16n8k16.row.col.f32.f16.f16.f32 "
        "{%0,%1,%2,%3}, {%4,%5,%6,%7}, {%8,%9}, {%0,%1,%2,%3};\n"
        : "+f"(d[0]), "+f"(d[1]), "+f"(d[2]), "+f"(d[3])
        : "r"(a[0]), "r"(a[1]), "r"(a[2]), "r"(a[3]), "r"(b0), "r"(b1));
}

// swizzled offset for (row, 16B-chunk cc):  row*128 + ((cc ^ (row&7)) << 4)
__device__ __forceinline__ uint32_t sw_off(int row, int cc) {
    return (uint32_t)(row * 128 + ((cc ^ (row & 7)) << 4));
}

// ---------------------------------------------------------------------------
// 2:4 soft-threshold prep, output TRANSPOSED to [N, K] fp16 (K-major).
// W: [Kd, Nd] row-major, groups of 4 along Nd (last dim).
// ---------------------------------------------------------------------------
__global__ void prep_weights_T(const float* __restrict__ W, const float* __restrict__ scale,
                               __half* __restrict__ Wt, int Kd, int Nd)
{
    int t = blockIdx.x * blockDim.x + threadIdx.x;
    int nk = Kd >> 2;
    if (t >= nk * (Nd >> 2)) return;
    int k0 = (t % nk) << 2;
    int n0 = (t / nk) << 2;
    float s = scale[0];
    __half o[4][4];
    #pragma unroll
    for (int i = 0; i < 4; i++) {
        float4 w = *reinterpret_cast<const float4*>(W + (size_t)(k0 + i) * Nd + n0);
        float a0 = fabsf(w.x), a1 = fabsf(w.y), a2 = fabsf(w.z), a3 = fabsf(w.w);
        float lo01 = fminf(a0, a1), hi01 = fmaxf(a0, a1);
        float lo23 = fminf(a2, a3), hi23 = fmaxf(a2, a3);
        float th = fminf(fmaxf(lo01, lo23), fminf(hi01, hi23));
        o[i][0] = __float2half(copysignf(fmaxf(a0 - th, 0.f), w.x) * s);
        o[i][1] = __float2half(copysignf(fmaxf(a1 - th, 0.f), w.y) * s);
        o[i][2] = __float2half(copysignf(fmaxf(a2 - th, 0.f), w.z) * s);
        o[i][3] = __float2half(copysignf(fmaxf(a3 - th, 0.f), w.w) * s);
    }
    #pragma unroll
    for (int j = 0; j < 4; j++) {
        __half2 p0 = __halves2half2(o[0][j], o[1][j]);
        __half2 p1 = __halves2half2(o[2][j], o[3][j]);
        uint2 u;
        u.x = *reinterpret_cast<uint32_t*>(&p0);
        u.y = *reinterpret_cast<uint32_t*>(&p1);
        *reinterpret_cast<uint2*>(Wt + (size_t)(n0 + j) * Kd + k0) = u;
    }
}

// ---------------------------------------------------------------------------
// GEMM1: h[16384,256] = fp16( x[16384,2048] @ wiT[256,2048]^T + bias )
// CTA 64x256 (full N -> x read once), BK=64, 8 warps (warp tile 32x64).
// A fp32: LDG->regs->cvt->STS (2 buffers, 8KB each). B: cp.async 3-stage 32KB.
// smem 112KB -> 2 CTAs/SM. grid 256.
// ---------------------------------------------------------------------------
__global__ __launch_bounds__(256, 2) void gemm1_kernel(
    const float* __restrict__ A, const __half* __restrict__ Bt,
    const float* __restrict__ bias, __half* __restrict__ C)
{
    constexpr int KT = 2048 / 64;  // 32
    extern __shared__ char smem[];
    const uint32_t sb = smem_u32(smem);
    const int tid = threadIdx.x, wid = tid >> 5, lane = tid & 31;
    const int wm = wid >> 2, wn = wid & 3;   // 2 x 4 warps, warp tile 32x64
    const int m0 = blockIdx.x * 64;

    auto Aoff = [&](int b) { return sb + b * 8192u; };            // 2 x 8KB
    auto Boff = [&](int s) { return sb + 16384u + s * 32768u; };  // 3 x 32KB

    // --- A: fp32 reg staging (thread -> quarter row: 16 floats) ---
    float4 aR[4];
    const int arow = tid >> 2, aq = tid & 3;
    auto ldgA = [&](int kt) {
        const float* p = A + (size_t)(m0 + arow) * 2048 + kt * 64 + aq * 16;
        #pragma unroll
        for (int j = 0; j < 4; j++) aR[j] = *reinterpret_cast<const float4*>(p + j * 4);
    };
    auto stsA = [&](int b) {
        #pragma unroll
        for (int half16 = 0; half16 < 2; half16++) {
            __half2 h0 = __floats2half2_rn(aR[2*half16].x,   aR[2*half16].y);
            __half2 h1 = __floats2half2_rn(aR[2*half16].z,   aR[2*half16].w);
            __half2 h2 = __floats2half2_rn(aR[2*half16+1].x, aR[2*half16+1].y);
            __half2 h3 = __floats2half2_rn(aR[2*half16+1].z, aR[2*half16+1].w);
            uint32_t u0 = *reinterpret_cast<uint32_t*>(&h0);
            uint32_t u1 = *reinterpret_cast<uint32_t*>(&h1);
            uint32_t u2 = *reinterpret_cast<uint32_t*>(&h2);
            uint32_t u3 = *reinterpret_cast<uint32_t*>(&h3);
            uint32_t dst = Aoff(b) + sw_off(arow, aq * 2 + half16);
            asm volatile("st.shared.v4.b32 [%0], {%1,%2,%3,%4};"
                         :: "r"(dst), "r"(u0), "r"(u1), "r"(u2), "r"(u3) : "memory");
        }
    };
    // --- B: cp.async, tile 256 rows x 128B ---
    auto ldB = [&](int kt, int s) {
        #pragma unroll
        for (int i = 0; i < 8; i++) {
            int c = tid + i * 256, row = c >> 3, cc = c & 7;
            CP_ASYNC16(Boff(s) + sw_off(row, cc),
                       Bt + (size_t)row * 2048 + kt * 64 + cc * 8);
        }
    };

    float acc[2][8][4];
    #pragma unroll
    for (int mi = 0; mi < 2; mi++)
        #pragma unroll
        for (int nn = 0; nn < 8; nn++)
            #pragma unroll
            for (int j = 0; j < 4; j++) acc[mi][nn][j] = 0.f;

    // Precompute ldsm row bases
    uint32_t aBase[2], bBase[4];
    int aX[2], bX[4];
    #pragma unroll
    for (int mi = 0; mi < 2; mi++) {
        int r = wm * 32 + mi * 16 + (lane & 15);
        aBase[mi] = (uint32_t)(r * 128); aX[mi] = r & 7;
    }
    #pragma unroll
    for (int ni = 0; ni < 4; ni++) {
        int r = wn * 64 + ni * 16 + (lane & 15);
        bBase[ni] = (uint32_t)(r * 128); bX[ni] = r & 7;
    }
    const int lhi = lane >> 4;

    auto compute = [&](int ab, int bs) {
        const uint32_t Ab = Aoff(ab), Bb = Boff(bs);
        #pragma unroll
        for (int ks = 0; ks < 4; ks++) {
            const int c = ks * 2 + lhi;
            uint32_t af[2][4], bf[4][4];
            #pragma unroll
            for (int mi = 0; mi < 2; mi++)
                ldsm4(af[mi], Ab + aBase[mi] + ((uint32_t)(c ^ aX[mi]) << 4));
            #pragma unroll
            for (int ni = 0; ni < 4; ni++)
                ldsm4(bf[ni], Bb + bBase[ni] + ((uint32_t)(c ^ bX[ni]) << 4));
            #pragma unroll
            for (int mi = 0; mi < 2; mi++)
                #pragma unroll
                for (int ni = 0; ni < 4; ni++) {
                    mma16816(acc[mi][2*ni],   af[mi], bf[ni][0], bf[ni][2]);
                    mma16816(acc[mi][2*ni+1], af[mi], bf[ni][1], bf[ni][3]);
                }
        }
    };

    // Prologue
    ldgA(0); stsA(0);
    ldB(0, 0); CP_COMMIT();
    ldB(1, 1); CP_COMMIT();
    ldgA(1);

    for (int kt = 0; kt < KT; kt++) {
        if (kt < KT - 1) cp_wait<1>(); else cp_wait<0>();
        __syncthreads();
        if (kt + 2 < KT) { ldB(kt + 2, (kt + 2) % 3); CP_COMMIT(); }
        compute(kt & 1, kt % 3);
        if (kt + 1 < KT) {
            stsA((kt + 1) & 1);
            if (kt + 2 < KT) ldgA(kt + 2);
        }
    }
    __syncthreads();

    // Epilogue: stage 64 x 264 halfs -> coalesced 16B stores
    __half* stg = reinterpret_cast<__half*>(smem);
    const int g = lane >> 2, tc = (lane & 3) * 2;
    #pragma unroll
    for (int mi = 0; mi < 2; mi++)
        #pragma unroll
        for (int nn = 0; nn < 8; nn++) {
            int row = wm * 32 + mi * 16 + g;
            int col = wn * 64 + (nn >> 1) * 16 + (nn & 1) * 8 + tc;
            float b0 = bias[col], b1 = bias[col + 1];
            *reinterpret_cast<__half2*>(stg + row * 264 + col) =
                __floats2half2_rn(acc[mi][nn][0] + b0, acc[mi][nn][1] + b1);
            *reinterpret_cast<__half2*>(stg + (row + 8) * 264 + col) =
                __floats2half2_rn(acc[mi][nn][2] + b0, acc[mi][nn][3] + b1);
        }
    __syncthreads();
    #pragma unroll
    for (int i = 0; i < 8; i++) {
        int idx = tid + i * 256;
        int row = idx >> 5, c = idx & 31;
        uint4 v = *reinterpret_cast<uint4*>(stg + row * 264 + c * 8);
        *reinterpret_cast<uint4*>(C + (size_t)(m0 + row) * 256 + c * 8) = v;
    }
}

// ---------------------------------------------------------------------------
// GEMM2: y[16384,2048] = fp32( h[16384,256] @ woT[2048,256]^T + bias )
// CTA 64x128, FULL K=256 resident: A 4x8KB (32KB) + B 4x16KB (64KB) = 96KB.
// 4 cp.async groups issued up front; wait<3..0> + sync + compute per chunk.
// 8 warps (2x4, warp tile 32x32). 2 CTAs/SM -> 16 warps/SM.
// ---------------------------------------------------------------------------
__global__ __launch_bounds__(256, 2) void gemm2_kernel(
    const __half* __restrict__ A, const __half* __restrict__ Bt,
    const float* __restrict__ bias, float* __restrict__ C)
{
    extern __shared__ char smem[];
    const uint32_t sb = smem_u32(smem);
    const int tid = threadIdx.x, wid = tid >> 5, lane = tid & 31;
    const int wm = wid >> 2, wn = wid & 3;   // 2 x 4 warps, warp tile 32x32
    const int m0 = blockIdx.x * 64;          // gridDim.x = 256 (m tiles)
    const int n0 = blockIdx.y * 128;         // gridDim.y = 16  (n tiles)

    auto Aoff = [&](int kt) { return sb + kt * 8192u; };            // 4 x 8KB
    auto Boff = [&](int kt) { return sb + 32768u + kt * 16384u; };  // 4 x 16KB

    auto ldTile = [&](int kt) {
        #pragma unroll
        for (int i = 0; i < 2; i++) {   // A: 64 rows x 8 chunks = 512
            int c = tid + i * 256, row = c >> 3, cc = c & 7;
            CP_ASYNC16(Aoff(kt) + sw_off(row, cc),
                       A + (size_t)(m0 + row) * 256 + kt * 64 + cc * 8);
        }
        #pragma unroll
        for (int i = 0; i < 4; i++) {   // B: 128 rows x 8 chunks = 1024
            int c = tid + i * 256, row = c >> 3, cc = c & 7;
            CP_ASYNC16(Boff(kt) + sw_off(row, cc),
                       Bt + (size_t)(n0 + row) * 256 + kt * 64 + cc * 8);
        }
        CP_COMMIT();
    };

    float acc[2][4][4];
    #pragma unroll
    for (int mi = 0; mi < 2; mi++)
        #pragma unroll
        for (int nn = 0; nn < 4; nn++)
            #pragma unroll
            for (int j = 0; j < 4; j++) acc[mi][nn][j] = 0.f;

    uint32_t aBase[2], bBase[2];
    int aX[2], bX[2];
    #pragma unroll
    for (int mi = 0; mi < 2; mi++) {
        int r = wm * 32 + mi * 16 + (lane & 15);
        aBase[mi] = (uint32_t)(r * 128); aX[mi] = r & 7;
    }
    #pragma unroll
    for (int ni = 0; ni < 2; ni++) {
        int r = wn * 32 + ni * 16 + (lane & 15);
        bBase[ni] = (uint32_t)(r * 128); bX[ni] = r & 7;
    }
    const int lhi = lane >> 4;

    auto compute = [&](int kt) {
        const uint32_t Ab = Aoff(kt), Bb = Boff(kt);
        #pragma unroll
        for (int ks = 0; ks < 4; ks++) {
            const int c = ks * 2 + lhi;
            uint32_t af[2][4], bf[2][4];
            #pragma unroll
            for (int mi = 0; mi < 2; mi++)
                ldsm4(af[mi], Ab + aBase[mi] + ((uint32_t)(c ^ aX[mi]) << 4));
            #pragma unroll
            for (int ni = 0; ni < 2; ni++)
                ldsm4(bf[ni], Bb + bBase[ni] + ((uint32_t)(c ^ bX[ni]) << 4));
            #pragma unroll
            for (int mi = 0; mi < 2; mi++)
                #pragma unroll
                for (int ni = 0; ni < 2; ni++) {
                    mma16816(acc[mi][2*ni],   af[mi], bf[ni][0], bf[ni][2]);
                    mma16816(acc[mi][2*ni+1], af[mi], bf[ni][1], bf[ni][3]);
                }
        }
    };

    // Issue ALL of K as 4 cp.async groups, then drain group-by-group.
    ldTile(0); ldTile(1); ldTile(2); ldTile(3);
    cp_wait<3>(); __syncthreads(); compute(0);
    cp_wait<2>(); __syncthreads(); compute(1);
    cp_wait<1>(); __syncthreads(); compute(2);
    cp_wait<0>(); __syncthreads(); compute(3);
    __syncthreads();

    // Epilogue: stage 64 x 132 fp32 -> coalesced 16B stores
    float* stg = reinterpret_cast<float*>(smem);
    const int g = lane >> 2, tc = (lane & 3) * 2;
    #pragma unroll
    for (int mi = 0; mi < 2; mi++)
        #pragma unroll
        for (int nn = 0; nn < 4; nn++) {
            int row = wm * 32 + mi * 16 + g;
            int col = wn * 32 + (nn >> 1) * 16 + (nn & 1) * 8 + tc;
            float b0 = bias[n0 + col], b1 = bias[n0 + col + 1];
            *reinterpret_cast<float2*>(stg + row * 132 + col) =
                make_float2(acc[mi][nn][0] + b0, acc[mi][nn][1] + b1);
            *reinterpret_cast<float2*>(stg + (row + 8) * 132 + col) =
                make_float2(acc[mi][nn][2] + b0, acc[mi][nn][3] + b1);
        }
    __syncthreads();
    #pragma unroll
    for (int i = 0; i < 8; i++) {
        int idx = tid + i * 256;
        int row = idx >> 5, c = idx & 31;
        uint4 v = *reinterpret_cast<uint4*>(stg + row * 132 + c * 4);
        *reinterpret_cast<uint4*>(C + (size_t)(m0 + row) * 2048 + n0 + c * 4) = v;
    }
}

// ---------------------------------------------------------------------------
extern "C" void kernel_launch(void* const* d_in, const int* in_sizes, int n_in,
                              void* d_out, int out_size)
{
    const float* x     = (const float*)d_in[0];
    const float* w_in  = (const float*)d_in[1];
    const float* w_out = (const float*)d_in[2];
    const float* b_in  = (const float*)d_in[3];
    const float* b_out = (const float*)d_in[4];
    const float* s_in  = (const float*)d_in[5];
    const float* s_out = (const float*)d_in[6];

    __half *wiT, *woT, *h;
    cudaGetSymbolAddress((void**)&wiT, g_wiT);
    cudaGetSymbolAddress((void**)&woT, g_woT);
    cudaGetSymbolAddress((void**)&h,   g_h);

    constexpr int SMEM1 = 16384 + 3 * 32768;  // 114688 (A 2x8KB + B 3x32KB)
    constexpr int SMEM2 = 32768 + 65536;      // 98304  (A 4x8KB + B 4x16KB)
    cudaFuncSetAttribute(gemm1_kernel, cudaFuncAttributeMaxDynamicSharedMemorySize, SMEM1);
    cudaFuncSetAttribute(gemm2_kernel, cudaFuncAttributeMaxDynamicSharedMemorySize, SMEM2);

    // Prep: 2:4 soft-threshold + scale + transpose to [N,K] fp16
    prep_weights_T<<<128, 256>>>(w_in,  s_in,  wiT, Dc, Rc);   // -> [256, 2048]
    prep_weights_T<<<128, 256>>>(w_out, s_out, woT, Rc, Dc);   // -> [2048, 256]

    // GEMM1: h = fp16(x @ wi + b_in); grid 256 CTAs (64 rows each), 2 CTAs/SM
    gemm1_kernel<<<dim3(256), 256, SMEM1>>>(x, wiT, b_in, h);

    // GEMM2: y = fp32(h @ wo + b_out); grid (256 m, 16 n) — m fastest varies?
    // dim3(a,b): blockIdx.x fastest => x = m tiles, consecutive CTAs share n? No:
    // consecutive blockIdx.x are different m, same n. We want same-m co-resident
    // for h L2 reuse — h is 8MB and fits L2 regardless, so ordering is secondary.
    gemm2_kernel<<<dim3(256, 16), 256, SMEM2>>>(h, woT, b_out, (float*)d_out);
}

// round 6
// speedup vs baseline: 1.0504x; 1.0172x over previous
#include <cuda_runtime.h>
#include <cuda_fp16.h>
#include <cstdint>

// Problem constants
constexpr int Dc = 2048, Rc = 256, NTOK = 16384;

// Scratch (no cudaMalloc allowed)
__device__ __half g_h[NTOK * Rc];       // intermediate h, fp16 (8 MB)
__device__ __half g_wiT[Rc * Dc];       // prepped weight_in,  transposed [N=R, K=D]
__device__ __half g_woT[Dc * Rc];       // prepped weight_out, transposed [N=D, K=R]

// ---------------------------------------------------------------------------
// Helpers
// ---------------------------------------------------------------------------
__device__ __forceinline__ uint32_t smem_u32(const void* p) {
    uint32_t a;
    asm("{ .reg .u64 t; cvta.to.shared.u64 t, %1; cvt.u32.u64 %0, t; }" : "=r"(a) : "l"(p));
    return a;
}

#define CP_ASYNC16(dst, src) asm volatile("cp.async.cg.shared.global [%0], [%1], 16;" :: "r"(dst), "l"(src))
#define CP_COMMIT()          asm volatile("cp.async.commit_group;" ::: "memory")
template <int N> __device__ __forceinline__ void cp_wait() {
    asm volatile("cp.async.wait_group %0;" :: "n"(N) : "memory");
}

__device__ __forceinline__ void ldsm4(uint32_t* r, uint32_t addr) {
    asm volatile("ldmatrix.sync.aligned.m8n8.x4.shared.b16 {%0,%1,%2,%3}, [%4];"
                 : "=r"(r[0]), "=r"(r[1]), "=r"(r[2]), "=r"(r[3]) : "r"(addr));
}
__device__ __forceinline__ void mma16816(float* d, const uint32_t* a,
                                         uint32_t b0, uint32_t b1) {
    asm volatile(
        "mma.sync.aligned.m16n8k16.row.col.f32.f16.f16.f32 "
        "{%0,%1,%2,%3}, {%4,%5,%6,%7}, {%8,%9}, {%0,%1,%2,%3};\n"
        : "+f"(d[0]), "+f"(d[1]), "+f"(d[2]), "+f"(d[3])
        : "r"(a[0]), "r"(a[1]), "r"(a[2]), "r"(a[3]), "r"(b0), "r"(b1));
}

// swizzled offset for (row, 16B-chunk cc):  row*128 + ((cc ^ (row&7)) << 4)
__device__ __forceinline__ uint32_t sw_off(int row, int cc) {
    return (uint32_t)(row * 128 + ((cc ^ (row & 7)) << 4));
}

// ---------------------------------------------------------------------------
// 2:4 soft-threshold prep for BOTH weights in one launch.
// Output TRANSPOSED to [N, K] fp16 (K-major). Groups of 4 along Nd (last dim).
// blocks [0,128): w_in (Kd=2048, Nd=256); blocks [128,256): w_out (Kd=256, Nd=2048)
// ---------------------------------------------------------------------------
__device__ __forceinline__ void prep_one(const float* __restrict__ W, float s,
                                         __half* __restrict__ Wt, int Kd, int Nd, int t)
{
    int nk = Kd >> 2;
    int k0 = (t % nk) << 2;
    int n0 = (t / nk) << 2;
    __half o[4][4];
    #pragma unroll
    for (int i = 0; i < 4; i++) {
        float4 w = *reinterpret_cast<const float4*>(W + (size_t)(k0 + i) * Nd + n0);
        float a0 = fabsf(w.x), a1 = fabsf(w.y), a2 = fabsf(w.z), a3 = fabsf(w.w);
        float lo01 = fminf(a0, a1), hi01 = fmaxf(a0, a1);
        float lo23 = fminf(a2, a3), hi23 = fmaxf(a2, a3);
        float th = fminf(fmaxf(lo01, lo23), fminf(hi01, hi23));
        o[i][0] = __float2half(copysignf(fmaxf(a0 - th, 0.f), w.x) * s);
        o[i][1] = __float2half(copysignf(fmaxf(a1 - th, 0.f), w.y) * s);
        o[i][2] = __float2half(copysignf(fmaxf(a2 - th, 0.f), w.z) * s);
        o[i][3] = __float2half(copysignf(fmaxf(a3 - th, 0.f), w.w) * s);
    }
    #pragma unroll
    for (int j = 0; j < 4; j++) {
        __half2 p0 = __halves2half2(o[0][j], o[1][j]);
        __half2 p1 = __halves2half2(o[2][j], o[3][j]);
        uint2 u;
        u.x = *reinterpret_cast<uint32_t*>(&p0);
        u.y = *reinterpret_cast<uint32_t*>(&p1);
        *reinterpret_cast<uint2*>(Wt + (size_t)(n0 + j) * Kd + k0) = u;
    }
}

__global__ void prep_both(const float* __restrict__ Wi, const float* __restrict__ si,
                          const float* __restrict__ Wo, const float* __restrict__ so,
                          __half* __restrict__ WiT, __half* __restrict__ WoT)
{
    if (blockIdx.x < 128) {
        int t = blockIdx.x * blockDim.x + threadIdx.x;         // 32768 = (2048/4)*(256/4)
        prep_one(Wi, si[0], WiT, Dc, Rc, t);
    } else {
        int t = (blockIdx.x - 128) * blockDim.x + threadIdx.x; // 32768 = (256/4)*(2048/4)
        prep_one(Wo, so[0], WoT, Rc, Dc, t);
    }
}

// ---------------------------------------------------------------------------
// GEMM1: h[16384,256] = fp16( x[16384,2048] @ wiT[256,2048]^T + bias )
// CTA 64x256 (full N -> x read once), BK=64, 8 warps (warp tile 32x64).
// A fp32: LDG->regs->cvt->STS (2 buffers, 8KB each). B: cp.async 3-stage 32KB.
// smem 112KB -> 2 CTAs/SM. grid 256.
// ---------------------------------------------------------------------------
__global__ __launch_bounds__(256, 2) void gemm1_kernel(
    const float* __restrict__ A, const __half* __restrict__ Bt,
    const float* __restrict__ bias, __half* __restrict__ C)
{
    constexpr int KT = 2048 / 64;  // 32
    extern __shared__ char smem[];
    const uint32_t sb = smem_u32(smem);
    const int tid = threadIdx.x, wid = tid >> 5, lane = tid & 31;
    const int wm = wid >> 2, wn = wid & 3;   // 2 x 4 warps, warp tile 32x64
    const int m0 = blockIdx.x * 64;

    auto Aoff = [&](int b) { return sb + b * 8192u; };            // 2 x 8KB
    auto Boff = [&](int s) { return sb + 16384u + s * 32768u; };  // 3 x 32KB

    // --- A: fp32 reg staging (thread -> quarter row: 16 floats) ---
    float4 aR[4];
    const int arow = tid >> 2, aq = tid & 3;
    auto ldgA = [&](int kt) {
        const float* p = A + (size_t)(m0 + arow) * 2048 + kt * 64 + aq * 16;
        #pragma unroll
        for (int j = 0; j < 4; j++) aR[j] = *reinterpret_cast<const float4*>(p + j * 4);
    };
    auto stsA = [&](int b) {
        #pragma unroll
        for (int half16 = 0; half16 < 2; half16++) {
            __half2 h0 = __floats2half2_rn(aR[2*half16].x,   aR[2*half16].y);
            __half2 h1 = __floats2half2_rn(aR[2*half16].z,   aR[2*half16].w);
            __half2 h2 = __floats2half2_rn(aR[2*half16+1].x, aR[2*half16+1].y);
            __half2 h3 = __floats2half2_rn(aR[2*half16+1].z, aR[2*half16+1].w);
            uint32_t u0 = *reinterpret_cast<uint32_t*>(&h0);
            uint32_t u1 = *reinterpret_cast<uint32_t*>(&h1);
            uint32_t u2 = *reinterpret_cast<uint32_t*>(&h2);
            uint32_t u3 = *reinterpret_cast<uint32_t*>(&h3);
            uint32_t dst = Aoff(b) + sw_off(arow, aq * 2 + half16);
            asm volatile("st.shared.v4.b32 [%0], {%1,%2,%3,%4};"
                         :: "r"(dst), "r"(u0), "r"(u1), "r"(u2), "r"(u3) : "memory");
        }
    };
    // --- B: cp.async, tile 256 rows x 128B ---
    auto ldB = [&](int kt, int s) {
        #pragma unroll
        for (int i = 0; i < 8; i++) {
            int c = tid + i * 256, row = c >> 3, cc = c & 7;
            CP_ASYNC16(Boff(s) + sw_off(row, cc),
                       Bt + (size_t)row * 2048 + kt * 64 + cc * 8);
        }
    };

    float acc[2][8][4];
    #pragma unroll
    for (int mi = 0; mi < 2; mi++)
        #pragma unroll
        for (int nn = 0; nn < 8; nn++)
            #pragma unroll
            for (int j = 0; j < 4; j++) acc[mi][nn][j] = 0.f;

    // Precompute ldsm row bases
    uint32_t aBase[2], bBase[4];
    int aX[2], bX[4];
    #pragma unroll
    for (int mi = 0; mi < 2; mi++) {
        int r = wm * 32 + mi * 16 + (lane & 15);
        aBase[mi] = (uint32_t)(r * 128); aX[mi] = r & 7;
    }
    #pragma unroll
    for (int ni = 0; ni < 4; ni++) {
        int r = wn * 64 + ni * 16 + (lane & 15);
        bBase[ni] = (uint32_t)(r * 128); bX[ni] = r & 7;
    }
    const int lhi = lane >> 4;

    auto compute = [&](int ab, int bs) {
        const uint32_t Ab = Aoff(ab), Bb = Boff(bs);
        #pragma unroll
        for (int ks = 0; ks < 4; ks++) {
            const int c = ks * 2 + lhi;
            uint32_t af[2][4], bf[4][4];
            #pragma unroll
            for (int mi = 0; mi < 2; mi++)
                ldsm4(af[mi], Ab + aBase[mi] + ((uint32_t)(c ^ aX[mi]) << 4));
            #pragma unroll
            for (int ni = 0; ni < 4; ni++)
                ldsm4(bf[ni], Bb + bBase[ni] + ((uint32_t)(c ^ bX[ni]) << 4));
            #pragma unroll
            for (int mi = 0; mi < 2; mi++)
                #pragma unroll
                for (int ni = 0; ni < 4; ni++) {
                    mma16816(acc[mi][2*ni],   af[mi], bf[ni][0], bf[ni][2]);
                    mma16816(acc[mi][2*ni+1], af[mi], bf[ni][1], bf[ni][3]);
                }
        }
    };

    // Prologue
    ldgA(0); stsA(0);
    ldB(0, 0); CP_COMMIT();
    ldB(1, 1); CP_COMMIT();
    ldgA(1);

    for (int kt = 0; kt < KT; kt++) {
        if (kt < KT - 1) cp_wait<1>(); else cp_wait<0>();
        __syncthreads();
        if (kt + 2 < KT) { ldB(kt + 2, (kt + 2) % 3); CP_COMMIT(); }
        compute(kt & 1, kt % 3);
        if (kt + 1 < KT) {
            stsA((kt + 1) & 1);
            if (kt + 2 < KT) ldgA(kt + 2);
        }
    }
    __syncthreads();

    // Epilogue: stage 64 x 264 halfs -> coalesced 16B stores
    __half* stg = reinterpret_cast<__half*>(smem);
    const int g = lane >> 2, tc = (lane & 3) * 2;
    #pragma unroll
    for (int mi = 0; mi < 2; mi++)
        #pragma unroll
        for (int nn = 0; nn < 8; nn++) {
            int row = wm * 32 + mi * 16 + g;
            int col = wn * 64 + (nn >> 1) * 16 + (nn & 1) * 8 + tc;
            float b0 = bias[col], b1 = bias[col + 1];
            *reinterpret_cast<__half2*>(stg + row * 264 + col) =
                __floats2half2_rn(acc[mi][nn][0] + b0, acc[mi][nn][1] + b1);
            *reinterpret_cast<__half2*>(stg + (row + 8) * 264 + col) =
                __floats2half2_rn(acc[mi][nn][2] + b0, acc[mi][nn][3] + b1);
        }
    __syncthreads();
    #pragma unroll
    for (int i = 0; i < 8; i++) {
        int idx = tid + i * 256;
        int row = idx >> 5, c = idx & 31;
        uint4 v = *reinterpret_cast<uint4*>(stg + row * 264 + c * 8);
        *reinterpret_cast<uint4*>(C + (size_t)(m0 + row) * 256 + c * 8) = v;
    }
}

// ---------------------------------------------------------------------------
// GEMM2: y[16384,2048] = fp32( h[16384,256] @ woT[2048,256]^T + bias )
// CTA 64x128, FULL K=256 resident: A 4x8KB (32KB) + B 4x16KB (64KB) = 96KB.
// 4 cp.async groups issued up front; wait<3..0> + sync + compute per chunk.
// 8 warps (2x4, warp tile 32x32). 2 CTAs/SM -> 16 warps/SM.
// grid (16 n-tiles, 256 m-tiles), n FASTEST: the 16 CTAs sharing one h tile
// are co-resident -> h served from L2 after first read.
// ---------------------------------------------------------------------------
__global__ __launch_bounds__(256, 2) void gemm2_kernel(
    const __half* __restrict__ A, const __half* __restrict__ Bt,
    const float* __restrict__ bias, float* __restrict__ C)
{
    extern __shared__ char smem[];
    const uint32_t sb = smem_u32(smem);
    const int tid = threadIdx.x, wid = tid >> 5, lane = tid & 31;
    const int wm = wid >> 2, wn = wid & 3;   // 2 x 4 warps, warp tile 32x32
    const int n0 = blockIdx.x * 128;         // gridDim.x = 16  (n tiles, fastest)
    const int m0 = blockIdx.y * 64;          // gridDim.y = 256 (m tiles)

    auto Aoff = [&](int kt) { return sb + kt * 8192u; };            // 4 x 8KB
    auto Boff = [&](int kt) { return sb + 32768u + kt * 16384u; };  // 4 x 16KB

    auto ldTile = [&](int kt) {
        #pragma unroll
        for (int i = 0; i < 2; i++) {   // A: 64 rows x 8 chunks = 512
            int c = tid + i * 256, row = c >> 3, cc = c & 7;
            CP_ASYNC16(Aoff(kt) + sw_off(row, cc),
                       A + (size_t)(m0 + row) * 256 + kt * 64 + cc * 8);
        }
        #pragma unroll
        for (int i = 0; i < 4; i++) {   // B: 128 rows x 8 chunks = 1024
            int c = tid + i * 256, row = c >> 3, cc = c & 7;
            CP_ASYNC16(Boff(kt) + sw_off(row, cc),
                       Bt + (size_t)(n0 + row) * 256 + kt * 64 + cc * 8);
        }
        CP_COMMIT();
    };

    float acc[2][4][4];
    #pragma unroll
    for (int mi = 0; mi < 2; mi++)
        #pragma unroll
        for (int nn = 0; nn < 4; nn++)
            #pragma unroll
            for (int j = 0; j < 4; j++) acc[mi][nn][j] = 0.f;

    uint32_t aBase[2], bBase[2];
    int aX[2], bX[2];
    #pragma unroll
    for (int mi = 0; mi < 2; mi++) {
        int r = wm * 32 + mi * 16 + (lane & 15);
        aBase[mi] = (uint32_t)(r * 128); aX[mi] = r & 7;
    }
    #pragma unroll
    for (int ni = 0; ni < 2; ni++) {
        int r = wn * 32 + ni * 16 + (lane & 15);
        bBase[ni] = (uint32_t)(r * 128); bX[ni] = r & 7;
    }
    const int lhi = lane >> 4;

    auto compute = [&](int kt) {
        const uint32_t Ab = Aoff(kt), Bb = Boff(kt);
        #pragma unroll
        for (int ks = 0; ks < 4; ks++) {
            const int c = ks * 2 + lhi;
            uint32_t af[2][4], bf[2][4];
            #pragma unroll
            for (int mi = 0; mi < 2; mi++)
                ldsm4(af[mi], Ab + aBase[mi] + ((uint32_t)(c ^ aX[mi]) << 4));
            #pragma unroll
            for (int ni = 0; ni < 2; ni++)
                ldsm4(bf[ni], Bb + bBase[ni] + ((uint32_t)(c ^ bX[ni]) << 4));
            #pragma unroll
            for (int mi = 0; mi < 2; mi++)
                #pragma unroll
                for (int ni = 0; ni < 2; ni++) {
                    mma16816(acc[mi][2*ni],   af[mi], bf[ni][0], bf[ni][2]);
                    mma16816(acc[mi][2*ni+1], af[mi], bf[ni][1], bf[ni][3]);
                }
        }
    };

    // Issue ALL of K as 4 cp.async groups, then drain group-by-group.
    ldTile(0); ldTile(1); ldTile(2); ldTile(3);
    cp_wait<3>(); __syncthreads(); compute(0);
    cp_wait<2>(); __syncthreads(); compute(1);
    cp_wait<1>(); __syncthreads(); compute(2);
    cp_wait<0>(); __syncthreads(); compute(3);

    // Bias (per-thread cols fixed) loaded before the stage barrier
    const int g = lane >> 2, tc = (lane & 3) * 2;
    float bv[4][2];
    #pragma unroll
    for (int nn = 0; nn < 4; nn++) {
        int col = wn * 32 + (nn >> 1) * 16 + (nn & 1) * 8 + tc;
        bv[nn][0] = bias[n0 + col];
        bv[nn][1] = bias[n0 + col + 1];
    }
    __syncthreads();

    // Epilogue: stage 64 x 132 fp32 -> coalesced 16B stores
    float* stg = reinterpret_cast<float*>(smem);
    #pragma unroll
    for (int mi = 0; mi < 2; mi++)
        #pragma unroll
        for (int nn = 0; nn < 4; nn++) {
            int row = wm * 32 + mi * 16 + g;
            int col = wn * 32 + (nn >> 1) * 16 + (nn & 1) * 8 + tc;
            *reinterpret_cast<float2*>(stg + row * 132 + col) =
                make_float2(acc[mi][nn][0] + bv[nn][0], acc[mi][nn][1] + bv[nn][1]);
            *reinterpret_cast<float2*>(stg + (row + 8) * 132 + col) =
                make_float2(acc[mi][nn][2] + bv[nn][0], acc[mi][nn][3] + bv[nn][1]);
        }
    __syncthreads();
    #pragma unroll
    for (int i = 0; i < 8; i++) {
        int idx = tid + i * 256;
        int row = idx >> 5, c = idx & 31;
        uint4 v = *reinterpret_cast<uint4*>(stg + row * 132 + c * 4);
        *reinterpret_cast<uint4*>(C + (size_t)(m0 + row) * 2048 + n0 + c * 4) = v;
    }
}

// ---------------------------------------------------------------------------
extern "C" void kernel_launch(void* const* d_in, const int* in_sizes, int n_in,
                              void* d_out, int out_size)
{
    const float* x     = (const float*)d_in[0];
    const float* w_in  = (const float*)d_in[1];
    const float* w_out = (const float*)d_in[2];
    const float* b_in  = (const float*)d_in[3];
    const float* b_out = (const float*)d_in[4];
    const float* s_in  = (const float*)d_in[5];
    const float* s_out = (const float*)d_in[6];

    __half *wiT, *woT, *h;
    cudaGetSymbolAddress((void**)&wiT, g_wiT);
    cudaGetSymbolAddress((void**)&woT, g_woT);
    cudaGetSymbolAddress((void**)&h,   g_h);

    constexpr int SMEM1 = 16384 + 3 * 32768;  // 114688 (A 2x8KB + B 3x32KB)
    constexpr int SMEM2 = 32768 + 65536;      // 98304  (A 4x8KB + B 4x16KB)
    cudaFuncSetAttribute(gemm1_kernel, cudaFuncAttributeMaxDynamicSharedMemorySize, SMEM1);
    cudaFuncSetAttribute(gemm2_kernel, cudaFuncAttributeMaxDynamicSharedMemorySize, SMEM2);

    // Prep both weights in one launch: 2:4 soft-threshold + scale + transpose
    prep_both<<<256, 256>>>(w_in, s_in, w_out, s_out, wiT, woT);

    // GEMM1: h = fp16(x @ wi + b_in); grid 256 CTAs (64 rows each), 2 CTAs/SM
    gemm1_kernel<<<dim3(256), 256, SMEM1>>>(x, wiT, b_in, h);

    // GEMM2: y = fp32(h @ wo + b_out); grid (16 n, 256 m), n fastest for h L2 reuse
    gemm2_kernel<<<dim3(16, 256), 256, SMEM2>>>(h, woT, b_out, (float*)d_out);
}